// round 1
// baseline (speedup 1.0000x reference)
#include <cuda_runtime.h>
#include <math.h>

#define NN 25000
#define NE 400000
#define ND 100
#define EDICT 16
#define HF 128

// ---------------- device scratch (static, no allocation) ----------------
__device__ float4 g_tabT[ND * 32];        // [d][f] -> 4 heads (proj_node transposed)
__device__ float4 g_s1[ND];               // dot(proj_node[d][h], a1)
__device__ float4 g_s2[ND];               // dot(proj_node[d][h], a2)
__device__ float4 g_s3[EDICT];            // dot(proj_edge[k][h], a3)
__device__ float4 g_lnedge[EDICT * 32];   // LN(proj_edge) rows, 16 x 128 floats
__device__ float4 g_segsum[NN];           // per-node per-head sum of exp(logit)
__device__ int    g_deg[NN];              // in-degree
__device__ float4 g_Wmat[NN * ND];        // [t][d] -> 4 heads of sum exp  (40MB)

// ---------------- zero scratch ----------------
__global__ void k_zero() {
    int i = blockIdx.x * blockDim.x + threadIdx.x;
    float4 z = make_float4(0.f, 0.f, 0.f, 0.f);
    if (i < NN * ND) g_Wmat[i] = z;
    if (i < NN) { g_segsum[i] = z; g_deg[i] = 0; }
}

// ---------------- build tables ----------------
// blocks 0..99: node dict rows; blocks 100..115: edge dict rows
__global__ void k_tables(const float* __restrict__ node_emb,
                         const float* __restrict__ edge_emb,
                         const float* __restrict__ W_t, const float* __restrict__ b_t,
                         const float* __restrict__ W_e, const float* __restrict__ b_e,
                         const float* __restrict__ a_w,
                         const float* __restrict__ gamma, const float* __restrict__ beta) {
    __shared__ float sh[128];
    __shared__ float red[8];
    int b = blockIdx.x;
    int tid = threadIdx.x;
    bool isnode = (b < ND);
    const float* emb  = isnode ? (node_emb + b * 128) : (edge_emb + (b - ND) * 128);
    const float* W    = isnode ? W_t : W_e;
    const float* bias = isnode ? b_t : b_e;

    sh[tid] = emb[tid];
    __syncthreads();

    float acc = bias[tid];
#pragma unroll 8
    for (int i = 0; i < 128; i++) acc += sh[i] * W[i * 128 + tid];

    int h = tid >> 5;
    int f = tid & 31;

    if (isnode) {
        ((float*)&g_tabT[b * 32 + f])[h] = acc;
        float u = acc * a_w[f];
        float v = acc * a_w[32 + f];
#pragma unroll
        for (int o = 16; o; o >>= 1) {
            u += __shfl_xor_sync(0xFFFFFFFFu, u, o);
            v += __shfl_xor_sync(0xFFFFFFFFu, v, o);
        }
        if (f == 0) {
            ((float*)&g_s1[b])[h] = u;
            ((float*)&g_s2[b])[h] = v;
        }
    } else {
        int k = b - ND;
        float u = acc * a_w[64 + f];
#pragma unroll
        for (int o = 16; o; o >>= 1) u += __shfl_xor_sync(0xFFFFFFFFu, u, o);
        if (f == 0) ((float*)&g_s3[k])[h] = u;

        // layer norm across the 128 threads of this block
        float s = acc;
#pragma unroll
        for (int o = 16; o; o >>= 1) s += __shfl_xor_sync(0xFFFFFFFFu, s, o);
        if (f == 0) red[h] = s;
        __syncthreads();
        float mu = (red[0] + red[1] + red[2] + red[3]) * (1.f / 128.f);
        float dd = acc - mu;
        float sq = dd * dd;
#pragma unroll
        for (int o = 16; o; o >>= 1) sq += __shfl_xor_sync(0xFFFFFFFFu, sq, o);
        if (f == 0) red[4 + h] = sq;
        __syncthreads();
        float var = (red[4] + red[5] + red[6] + red[7]) * (1.f / 128.f);
        float val = dd * rsqrtf(var + 1e-5f) * gamma[tid] + beta[tid];
        ((float*)g_lnedge)[k * 128 + tid] = val;
    }
}

// ---------------- per-edge pass: exp(logit) accumulation ----------------
__global__ void k_edges(const int* __restrict__ nf, const int* __restrict__ ef,
                        const int* __restrict__ ei, const float* __restrict__ a_b) {
    int e = blockIdx.x * blockDim.x + threadIdx.x;
    if (e >= NE) return;
    int s = ei[e];
    int t = ei[NE + e];
    int k = ef[e];
    int ds = nf[s];
    int dt = nf[t];
    float ab = *a_b;
    float4 z1 = g_s1[dt];
    float4 z2 = g_s2[ds];
    float4 z3 = g_s3[k];

    float zx = z1.x + z2.x + z3.x + ab;
    float zy = z1.y + z2.y + z3.y + ab;
    float zz = z1.z + z2.z + z3.z + ab;
    float zw = z1.w + z2.w + z3.w + ab;
    // leaky relu
    zx = zx >= 0.f ? zx : 0.2f * zx;
    zy = zy >= 0.f ? zy : 0.2f * zy;
    zz = zz >= 0.f ? zz : 0.2f * zz;
    zw = zw >= 0.f ? zw : 0.2f * zw;
    float ex = __expf(zx), ey = __expf(zy), ez = __expf(zz), ew = __expf(zw);

    float* wp = (float*)&g_Wmat[t * ND + ds];
    atomicAdd(wp + 0, ex);
    atomicAdd(wp + 1, ey);
    atomicAdd(wp + 2, ez);
    atomicAdd(wp + 3, ew);
    float* sp = (float*)&g_segsum[t];
    atomicAdd(sp + 0, ex);
    atomicAdd(sp + 1, ey);
    atomicAdd(sp + 2, ez);
    atomicAdd(sp + 3, ew);
    atomicAdd(&g_deg[t], 1);
}

// ---------------- per-node recombine + layernorm ----------------
__global__ void k_nodes(const int* __restrict__ nf,
                        const float* __restrict__ gamma, const float* __restrict__ beta,
                        float* __restrict__ out) {
    int gw = (blockIdx.x * blockDim.x + threadIdx.x) >> 5;
    int l = threadIdx.x & 31;
    if (gw >= NN) return;
    int t = gw;

    float a0 = 0.f, a1 = 0.f, a2 = 0.f, a3 = 0.f;
    const float4* wrow = &g_Wmat[t * ND];
#pragma unroll 4
    for (int d = 0; d < ND; d++) {
        float4 w = wrow[d];  // uniform across warp -> broadcast
        if (w.x != 0.f || w.y != 0.f || w.z != 0.f || w.w != 0.f) {
            float4 p = g_tabT[d * 32 + l];
            a0 += w.x * p.x;
            a1 += w.y * p.y;
            a2 += w.z * p.z;
            a3 += w.w * p.w;
        }
    }
    float4 ss = g_segsum[t];
    float r0 = ss.x > 0.f ? 1.f / ss.x : 0.f;
    float r1 = ss.y > 0.f ? 1.f / ss.y : 0.f;
    float r2 = ss.z > 0.f ? 1.f / ss.z : 0.f;
    float r3 = ss.w > 0.f ? 1.f / ss.w : 0.f;

    int dt = nf[t];
    float4 p = g_tabT[dt * 32 + l];
    float dg = (float)g_deg[t];

    float v0 = a0 * r0 + dg * p.x;
    float v1 = a1 * r1 + dg * p.y;
    float v2 = a2 * r2 + dg * p.z;
    float v3 = a3 * r3 + dg * p.w;

    // layer norm over the 128 values held by this warp (4 per lane)
    float s = v0 + v1 + v2 + v3;
#pragma unroll
    for (int o = 16; o; o >>= 1) s += __shfl_xor_sync(0xFFFFFFFFu, s, o);
    float mu = s * (1.f / 128.f);
    float d0 = v0 - mu, d1 = v1 - mu, d2 = v2 - mu, d3 = v3 - mu;
    float sq = d0 * d0 + d1 * d1 + d2 * d2 + d3 * d3;
#pragma unroll
    for (int o = 16; o; o >>= 1) sq += __shfl_xor_sync(0xFFFFFFFFu, sq, o);
    float var = sq * (1.f / 128.f);
    float rs = rsqrtf(var + 1e-5f);

    float* o0 = out + (size_t)t * 128;
    o0[l]      = d0 * rs * gamma[l]      + beta[l];
    o0[32 + l] = d1 * rs * gamma[32 + l] + beta[32 + l];
    o0[64 + l] = d2 * rs * gamma[64 + l] + beta[64 + l];
    o0[96 + l] = d3 * rs * gamma[96 + l] + beta[96 + l];
}

// ---------------- edge output: broadcast-gather of 16 LN'd rows ----------------
__global__ void k_edgeout(const int* __restrict__ ef, float4* __restrict__ outE) {
    int i = blockIdx.x * blockDim.x + threadIdx.x;
    if (i >= NE * 32) return;
    int e = i >> 5;
    int c = i & 31;
    int k = ef[e];
    outE[(size_t)e * 32 + c] = g_lnedge[k * 32 + c];
}

// ---------------- launch ----------------
extern "C" void kernel_launch(void* const* d_in, const int* in_sizes, int n_in,
                              void* d_out, int out_size) {
    const int*   nf       = (const int*)d_in[0];
    const int*   ef       = (const int*)d_in[1];
    const int*   ei       = (const int*)d_in[2];
    const float* node_emb = (const float*)d_in[3];
    const float* edge_emb = (const float*)d_in[4];
    const float* W_t      = (const float*)d_in[5];
    const float* b_t      = (const float*)d_in[6];
    const float* W_e      = (const float*)d_in[7];
    const float* b_e      = (const float*)d_in[8];
    const float* a_w      = (const float*)d_in[9];
    const float* a_b      = (const float*)d_in[10];
    const float* gamma    = (const float*)d_in[11];
    const float* beta     = (const float*)d_in[12];

    float* out_node = (float*)d_out;                       // [25000, 128]
    float4* out_edge = (float4*)((float*)d_out + (size_t)NN * 128);  // [400000, 128]

    k_zero<<<(NN * ND + 255) / 256, 256>>>();
    k_tables<<<ND + EDICT, 128>>>(node_emb, edge_emb, W_t, b_t, W_e, b_e, a_w, gamma, beta);
    k_edges<<<(NE + 255) / 256, 256>>>(nf, ef, ei, a_b);
    k_nodes<<<(NN * 32 + 255) / 256, 256>>>(nf, gamma, beta, out_node);
    k_edgeout<<<(NE * 32 + 255) / 256, 256>>>(ef, out_edge);
}